// round 16
// baseline (speedup 1.0000x reference)
#include <cuda_runtime.h>
#include <cuda_bf16.h>
#include <mma.h>
using namespace nvcuda;

#define B_    16
#define TQ_   128
#define TK_   128
#define EMB_  256
#define HID_  100
#define F2E_  512   // 2*EMB
#define MROWS (B_ * TK_)          // 2048
#define XROWS (2 * MROWS)         // 4096 fused (keys || queries)

// Scratch (allocation-free rule: __device__ globals)
__device__ float g_A[MROWS * HID_];            // A[b][i][h]
__device__ float g_Ct[B_ * HID_ * TQ_];        // C^T[b][h][j] (includes +b1)
__device__ __nv_bfloat16 g_W1hi[128 * F2E_];   // W1 padded to 128 rows, split
__device__ __nv_bfloat16 g_W1lo[128 * F2E_];
__device__ __nv_bfloat16 g_Wlhi[EMB_ * F2E_];  // Wlast split
__device__ __nv_bfloat16 g_Wllo[EMB_ * F2E_];
__device__ __nv_bfloat16 g_fhi[MROWS * F2E_];  // features split
__device__ __nv_bfloat16 g_flo[MROWS * F2E_];
__device__ __nv_bfloat16 g_Phi[MROWS * TQ_];   // softmax P split
__device__ __nv_bfloat16 g_Plo[MROWS * TQ_];

__device__ __forceinline__ float ftanh(float x) {
    float y;
    asm("tanh.approx.f32 %0, %1;" : "=f"(y) : "f"(x));
    return y;
}

__device__ __forceinline__ void bsplit(float v, __nv_bfloat16& hi,
                                       __nv_bfloat16& lo) {
    hi = __float2bfloat16(v);
    lo = __float2bfloat16(v - __bfloat162float(hi));
}

// split 4 floats -> 4 bf16 hi + 4 bf16 lo at the given addrs
__device__ __forceinline__ void split4_store(float4 v, __nv_bfloat16* hi,
                                             __nv_bfloat16* lo) {
    __nv_bfloat16 h0, h1, h2, h3, l0, l1, l2, l3;
    bsplit(v.x, h0, l0); bsplit(v.y, h1, l1);
    bsplit(v.z, h2, l2); bsplit(v.w, h3, l3);
    *(__nv_bfloat162*)(hi)     = __nv_bfloat162{h0, h1};
    *(__nv_bfloat162*)(hi + 2) = __nv_bfloat162{h2, h3};
    *(__nv_bfloat162*)(lo)     = __nv_bfloat162{l0, l1};
    *(__nv_bfloat162*)(lo + 2) = __nv_bfloat162{l2, l3};
}

// ---------------------------------------------------------------------------
// K0: split W1 (pad 100->128 rows) and Wlast ONLY (weights are reused across
// many GEMM m-tiles; inputs are split inline by their consumers).
// ---------------------------------------------------------------------------
__global__ void split_weights(const float* __restrict__ W1,
                              const float* __restrict__ Wlast) {
    int i = blockIdx.x * 256 + threadIdx.x;   // < 196608
    if (i < 128 * F2E_) {
        int h = i >> 9;
        float v = (h < HID_) ? W1[i] : 0.f;
        bsplit(v, g_W1hi[i], g_W1lo[i]);
    } else {
        int j = i - 128 * F2E_;
        bsplit(Wlast[j], g_Wlhi[j], g_Wllo[j]);
    }
}

#define ALD 48
#define BLD 48
#define CLD 68

typedef wmma::fragment<wmma::matrix_a, 16, 16, 16, __nv_bfloat16,
                       wmma::row_major> FragA;
typedef wmma::fragment<wmma::matrix_b, 16, 16, 16, __nv_bfloat16,
                       wmma::col_major> FragB;
typedef wmma::fragment<wmma::matrix_b, 16, 16, 16, __nv_bfloat16,
                       wmma::row_major> FragBr;
typedef wmma::fragment<wmma::accumulator, 16, 16, 16, float> FragC;

// ---------------------------------------------------------------------------
// K1: prep GEMM. A (keys/queries) split inline from fp32; W1 pre-split.
// Fused M=4096 rows (keys -> g_A; queries -> g_Ct + b1).
// grid (2 n-tiles, 128 m-tiles) = 256 blocks, 256 threads.
// ---------------------------------------------------------------------------
__global__ void __launch_bounds__(256) prep_bf16(
        const float* __restrict__ queries,
        const float* __restrict__ keys,
        const float* __restrict__ b1) {
    __shared__ __align__(16) __nv_bfloat16 Ah[2][32 * ALD], Al[2][32 * ALD];
    __shared__ __align__(16) __nv_bfloat16 Bh[2][64 * BLD], Bl[2][64 * BLD];
    __shared__ __align__(16) float cs[32 * CLD];

    int m0g = blockIdx.y * 32;
    int side = m0g >= MROWS;
    int m0 = m0g & (MROWS - 1);
    int n0 = blockIdx.x * 64;
    const float* Xp = side ? queries : keys;

    int tid = threadIdx.x;
    int ar = tid >> 3, ac = (tid & 7) * 4;   // A stage: 32 rows x 32 k
    int br = tid >> 2, bc = (tid & 3) * 8;   // B stage: 64 rows x 32 k
    int w = tid >> 5, wm = w & 1, wn = w >> 1;

    const float* A_src = Xp + (m0 + ar) * EMB_ + ac;
    const __nv_bfloat16* Bh_src = g_W1hi + (n0 + br) * F2E_ + side * EMB_ + bc;
    const __nv_bfloat16* Bl_src = g_W1lo + (n0 + br) * F2E_ + side * EMB_ + bc;

    FragC c;
    wmma::fill_fragment(c, 0.f);
    FragA a_hi, a_lo;
    FragB b_hi, b_lo;

    float4 af = *(const float4*)A_src;
    uint4 bvh = *(const uint4*)Bh_src;
    uint4 bvl = *(const uint4*)Bl_src;
    split4_store(af, &Ah[0][ar * ALD + ac], &Al[0][ar * ALD + ac]);
    *(uint4*)&Bh[0][br * BLD + bc] = bvh;
    *(uint4*)&Bl[0][br * BLD + bc] = bvl;
    __syncthreads();

    const int NT = EMB_ / 32;  // 8
    #pragma unroll 1
    for (int t = 0; t < NT; ++t) {
        if (t + 1 < NT) {
            int k0 = (t + 1) * 32;
            af  = *(const float4*)(A_src + k0);
            bvh = *(const uint4*)(Bh_src + k0);
            bvl = *(const uint4*)(Bl_src + k0);
        }
        int bsel = t & 1;
        #pragma unroll
        for (int kk = 0; kk < 32; kk += 16) {
            wmma::load_matrix_sync(a_hi, &Ah[bsel][(wm * 16) * ALD + kk], ALD);
            wmma::load_matrix_sync(a_lo, &Al[bsel][(wm * 16) * ALD + kk], ALD);
            wmma::load_matrix_sync(b_hi, &Bh[bsel][(wn * 16) * BLD + kk], BLD);
            wmma::load_matrix_sync(b_lo, &Bl[bsel][(wn * 16) * BLD + kk], BLD);
            wmma::mma_sync(c, a_hi, b_hi, c);
            wmma::mma_sync(c, a_hi, b_lo, c);
            wmma::mma_sync(c, a_lo, b_hi, c);
        }
        if (t + 1 < NT) {
            int nb = (t + 1) & 1;
            split4_store(af, &Ah[nb][ar * ALD + ac], &Al[nb][ar * ALD + ac]);
            *(uint4*)&Bh[nb][br * BLD + bc] = bvh;
            *(uint4*)&Bl[nb][br * BLD + bc] = bvl;
            __syncthreads();
        }
    }
    __syncthreads();
    wmma::store_matrix_sync(cs + (wm * 16) * CLD + wn * 16, c, CLD,
                            wmma::mem_row_major);
    __syncthreads();

    for (int e = tid; e < 32 * 64; e += 256) {
        int rw = e >> 6, col = e & 63;
        int h = n0 + col;
        if (h < HID_) {
            float v = cs[rw * CLD + col];
            int row = m0 + rw;
            if (!side) {
                g_A[row * HID_ + h] = v;
            } else {
                int b = row >> 7, j = row & 127;
                g_Ct[(b * HID_ + h) * TQ_ + j] = v + b1[h];
            }
        }
    }
}

// ---------------------------------------------------------------------------
// K2a: score MLP + softmax -> P (bf16 hi/lo), km folded in.
// One block per (b, 4-row i-tile): grid (32, 16) = 512 blocks, 256 threads.
// Full c-panel staged in smem; each thread computes 2 adjacent j for one row.
// ---------------------------------------------------------------------------
#define ITILE 4
#define PST   5

__global__ void __launch_bounds__(256) sim_kernel(
        const float* __restrict__ qmask,
        const float* __restrict__ kmask,
        const float* __restrict__ W2) {
    extern __shared__ __align__(16) float sm[];
    float* c_s  = sm;                         // 12800
    float* a_s  = c_s + HID_ * TQ_;           // 400
    float* w2_s = a_s + ITILE * HID_;         // 104
    float* km_s = w2_s + 104;                 // 4
    float* p_s  = km_s + 4;                   // 128*5 = 640

    int b  = blockIdx.y;
    int i0 = blockIdx.x * ITILE;
    int tid = threadIdx.x;

    {   // cooperative c-panel stage (float4, coalesced)
        const float4* src = (const float4*)(g_Ct + b * HID_ * TQ_);
        float4* dst = (float4*)c_s;
        #pragma unroll
        for (int s = 0; s < 13; ++s) {
            int idx = tid + 256 * s;
            if (idx < (HID_ * TQ_) / 4) dst[idx] = src[idx];
        }
    }
    for (int idx = tid; idx < ITILE * HID_; idx += 256)
        a_s[idx] = g_A[(b * TK_ + i0 + (idx / HID_)) * HID_ + (idx % HID_)];
    if (tid < HID_)  w2_s[tid] = W2[tid];
    if (tid < ITILE) km_s[tid] = kmask[b * TK_ + i0 + tid];

    int j  = (tid & 63) * 2;   // query pair (j, j+1)
    int r  = tid >> 6;         // i-row (0..3)
    float2 qm2 = *(const float2*)(qmask + b * TQ_ + j);
    __syncthreads();

    // ---- phase 1: sim[r][j(+1)] = sum_h tanh(a[r,h] + c[h,j(+1)]) * w2[h]
    const float* ar_ = a_s + r * HID_;
    float acc0 = 0.f, acc1 = 0.f;
    #pragma unroll 4
    for (int h = 0; h < HID_; ++h) {
        float2 c2 = *(const float2*)&c_s[h * TQ_ + j];
        float av = ar_[h];
        float w  = w2_s[h];
        acc0 = fmaf(w, ftanh(av + c2.x), acc0);
        acc1 = fmaf(w, ftanh(av + c2.y), acc1);
    }
    const float NEGC = -4294967295.0f;  // -2^32 + 1
    p_s[j * PST + r]       = (qm2.x == 0.0f) ? NEGC : acc0;
    p_s[(j + 1) * PST + r] = (qm2.y == 0.0f) ? NEGC : acc1;
    __syncthreads();

    // ---- phase 2: softmax over j; warps 0..3 own rows 0..3, write P direct
    int warp = tid >> 5, lane = tid & 31;
    if (warp < ITILE) {
        int ii = warp;
        float v[4];
        float m = -3.4e38f;
        #pragma unroll
        for (int q = 0; q < 4; ++q) {
            v[q] = p_s[(lane + 32 * q) * PST + ii];
            m = fmaxf(m, v[q]);
        }
        #pragma unroll
        for (int off = 16; off; off >>= 1)
            m = fmaxf(m, __shfl_xor_sync(0xffffffffu, m, off));
        float ssum = 0.f;
        #pragma unroll
        for (int q = 0; q < 4; ++q) { v[q] = __expf(v[q] - m); ssum += v[q]; }
        #pragma unroll
        for (int off = 16; off; off >>= 1)
            ssum += __shfl_xor_sync(0xffffffffu, ssum, off);
        float scale = km_s[ii] / ssum;   // fold key_mask scalar into P
        int prow = (b * TK_ + i0 + ii) * TQ_;
        #pragma unroll
        for (int q = 0; q < 4; ++q) {
            __nv_bfloat16 hi, lo;
            bsplit(v[q] * scale, hi, lo);
            g_Phi[prow + lane + 32 * q] = hi;
            g_Plo[prow + lane + 32 * q] = lo;
        }
    }
}

// ---------------------------------------------------------------------------
// K2b: keys_attn = P @ queries (bf16 hi/lo tensor GEMM, K=128) + feature
// epilogue. Queries split inline from fp32 during staging.
// M=2048 (key rows), N=256 (emb). grid (4 n-tiles, 64 m-tiles).
// ---------------------------------------------------------------------------
#define PALD 136   // A smem ldm (bf16): 272B rows
#define PBLD 72    // B smem ldm (bf16): 144B rows

__global__ void __launch_bounds__(256) pv_kernel(
        const float* __restrict__ queries,
        const float* __restrict__ keys) {
    __shared__ __align__(16) __nv_bfloat16 Ah[32 * PALD], Al[32 * PALD];
    __shared__ __align__(16) __nv_bfloat16 Bh[TQ_ * PBLD], Bl[TQ_ * PBLD];
    __shared__ __align__(16) float cs[32 * CLD];

    int m0 = blockIdx.y * 32;          // global key row
    int n0 = blockIdx.x * 64;          // emb col
    int b  = m0 >> 7;
    int tid = threadIdx.x;
    int w = tid >> 5, wm = w & 1, wn = w >> 1;

    // prefetch epilogue keys (8 per thread) to overlap with staging + MMA
    int col0 = tid & 63, rw0 = tid >> 6;
    float kv[8];
    #pragma unroll
    for (int s = 0; s < 8; ++s)
        kv[s] = __ldg(keys + (m0 + rw0 + 4 * s) * EMB_ + n0 + col0);

    // stage A = P[m0..m0+31][0..127] (hi/lo, already bf16)
    #pragma unroll
    for (int s = 0; s < 2; ++s) {
        int cidx = tid + 256 * s;          // 512 chunks of 8
        int r = cidx >> 4, c8 = (cidx & 15) * 8;
        *(uint4*)&Ah[r * PALD + c8] = *(const uint4*)&g_Phi[(m0 + r) * TQ_ + c8];
        *(uint4*)&Al[r * PALD + c8] = *(const uint4*)&g_Plo[(m0 + r) * TQ_ + c8];
    }
    // stage B = queries_b[0..127][n0..n0+63], split inline from fp32
    #pragma unroll
    for (int s = 0; s < 4; ++s) {
        int cidx = tid + 256 * s;          // 1024 chunks of 8
        int r = cidx >> 3, c8 = (cidx & 7) * 8;
        const float* q = queries + (b * TQ_ + r) * EMB_ + n0 + c8;
        split4_store(*(const float4*)q,
                     &Bh[r * PBLD + c8], &Bl[r * PBLD + c8]);
        split4_store(*(const float4*)(q + 4),
                     &Bh[r * PBLD + c8 + 4], &Bl[r * PBLD + c8 + 4]);
    }
    __syncthreads();

    FragC c;
    wmma::fill_fragment(c, 0.f);
    FragA a_hi, a_lo;
    FragBr b_hi, b_lo;
    #pragma unroll
    for (int kk = 0; kk < TQ_; kk += 16) {
        wmma::load_matrix_sync(a_hi, &Ah[(wm * 16) * PALD + kk], PALD);
        wmma::load_matrix_sync(a_lo, &Al[(wm * 16) * PALD + kk], PALD);
        wmma::load_matrix_sync(b_hi, &Bh[kk * PBLD + wn * 16], PBLD);
        wmma::load_matrix_sync(b_lo, &Bl[kk * PBLD + wn * 16], PBLD);
        wmma::mma_sync(c, a_hi, b_hi, c);
        wmma::mma_sync(c, a_hi, b_lo, c);
        wmma::mma_sync(c, a_lo, b_hi, c);
    }
    __syncthreads();
    wmma::store_matrix_sync(cs + (wm * 16) * CLD + wn * 16, c, CLD,
                            wmma::mem_row_major);
    __syncthreads();

    // feature epilogue: fm = ka*kv, fs = (ka-kv)^2, split to bf16
    #pragma unroll
    for (int s = 0; s < 8; ++s) {
        int rw = rw0 + 4 * s, col = col0;
        float ka = cs[rw * CLD + col];
        int row = m0 + rw;
        float fm = ka * kv[s];
        float d  = ka - kv[s];
        float fs = d * d;
        __nv_bfloat16 hi, lo;
        bsplit(fm, hi, lo);
        g_fhi[row * F2E_ + n0 + col] = hi;
        g_flo[row * F2E_ + n0 + col] = lo;
        bsplit(fs, hi, lo);
        g_fhi[row * F2E_ + EMB_ + n0 + col] = hi;
        g_flo[row * F2E_ + EMB_ + n0 + col] = lo;
    }
}

// ---------------------------------------------------------------------------
// K3: out = relu(feat[2048,512] @ Wlast[256,512]^T + blast).
// feat and Wlast both pre-split bf16. grid (4, 64) = 256 blocks.
// ---------------------------------------------------------------------------
__global__ void __launch_bounds__(256) gemm_bf16(
        const float* __restrict__ blast,
        float* __restrict__ out) {
    __shared__ __align__(16) __nv_bfloat16 Ah[2][32 * ALD], Al[2][32 * ALD];
    __shared__ __align__(16) __nv_bfloat16 Bh[2][64 * BLD], Bl[2][64 * BLD];
    __shared__ __align__(16) float cs[32 * CLD];

    int m0 = blockIdx.y * 32;
    int n0 = blockIdx.x * 64;
    int tid = threadIdx.x;
    int ar = tid >> 3, ac = (tid & 7) * 4;
    int br = tid >> 2, bc = (tid & 3) * 8;
    int w = tid >> 5, wm = w & 1, wn = w >> 1;

    const __nv_bfloat16* Ah_src = g_fhi + (m0 + ar) * F2E_ + ac;
    const __nv_bfloat16* Al_src = g_flo + (m0 + ar) * F2E_ + ac;
    const __nv_bfloat16* Bh_src = g_Wlhi + (n0 + br) * F2E_ + bc;
    const __nv_bfloat16* Bl_src = g_Wllo + (n0 + br) * F2E_ + bc;

    FragC c;
    wmma::fill_fragment(c, 0.f);
    FragA a_hi, a_lo;
    FragB b_hi, b_lo;

    uint2 avh = *(const uint2*)Ah_src;
    uint2 avl = *(const uint2*)Al_src;
    uint4 bvh = *(const uint4*)Bh_src;
    uint4 bvl = *(const uint4*)Bl_src;
    *(uint2*)&Ah[0][ar * ALD + ac] = avh;
    *(uint2*)&Al[0][ar * ALD + ac] = avl;
    *(uint4*)&Bh[0][br * BLD + bc] = bvh;
    *(uint4*)&Bl[0][br * BLD + bc] = bvl;
    __syncthreads();

    const int NT = F2E_ / 32;  // 16
    #pragma unroll 1
    for (int t = 0; t < NT; ++t) {
        if (t + 1 < NT) {
            int k0 = (t + 1) * 32;
            avh = *(const uint2*)(Ah_src + k0);
            avl = *(const uint2*)(Al_src + k0);
            bvh = *(const uint4*)(Bh_src + k0);
            bvl = *(const uint4*)(Bl_src + k0);
        }
        int bsel = t & 1;
        #pragma unroll
        for (int kk = 0; kk < 32; kk += 16) {
            wmma::load_matrix_sync(a_hi, &Ah[bsel][(wm * 16) * ALD + kk], ALD);
            wmma::load_matrix_sync(a_lo, &Al[bsel][(wm * 16) * ALD + kk], ALD);
            wmma::load_matrix_sync(b_hi, &Bh[bsel][(wn * 16) * BLD + kk], BLD);
            wmma::load_matrix_sync(b_lo, &Bl[bsel][(wn * 16) * BLD + kk], BLD);
            wmma::mma_sync(c, a_hi, b_hi, c);
            wmma::mma_sync(c, a_hi, b_lo, c);
            wmma::mma_sync(c, a_lo, b_hi, c);
        }
        if (t + 1 < NT) {
            int nb = (t + 1) & 1;
            *(uint2*)&Ah[nb][ar * ALD + ac] = avh;
            *(uint2*)&Al[nb][ar * ALD + ac] = avl;
            *(uint4*)&Bh[nb][br * BLD + bc] = bvh;
            *(uint4*)&Bl[nb][br * BLD + bc] = bvl;
            __syncthreads();
        }
    }
    __syncthreads();
    wmma::store_matrix_sync(cs + (wm * 16) * CLD + wn * 16, c, CLD,
                            wmma::mem_row_major);
    __syncthreads();

    for (int e = tid; e < 32 * 64; e += 256) {
        int rw = e >> 6, col = e & 63;
        float v = cs[rw * CLD + col] + blast[n0 + col];
        out[(m0 + rw) * EMB_ + n0 + col] = fmaxf(v, 0.f);
    }
}

// ---------------------------------------------------------------------------
extern "C" void kernel_launch(void* const* d_in, const int* in_sizes, int n_in,
                              void* d_out, int out_size) {
    const float* queries = (const float*)d_in[0];
    const float* keys    = (const float*)d_in[1];
    const float* qmask   = (const float*)d_in[2];
    const float* kmask   = (const float*)d_in[3];
    const float* W1      = (const float*)d_in[4];
    const float* b1      = (const float*)d_in[5];
    const float* W2      = (const float*)d_in[6];
    const float* Wlast   = (const float*)d_in[7];
    const float* blast   = (const float*)d_in[8];
    float* out = (float*)d_out;

    const int smem_sim = (HID_ * TQ_ + ITILE * HID_ + 104 + ITILE + TQ_ * PST) * 4;
    cudaFuncSetAttribute(sim_kernel, cudaFuncAttributeMaxDynamicSharedMemorySize,
                         smem_sim);

    split_weights<<<(128 * F2E_ + EMB_ * F2E_) / 256, 256>>>(W1, Wlast);
    prep_bf16<<<dim3(2, XROWS / 32), 256>>>(queries, keys, b1);
    sim_kernel<<<dim3(TK_ / ITILE, B_), 256, smem_sim>>>(qmask, kmask, W2);
    pv_kernel<<<dim3(EMB_ / 64, MROWS / 32), 256>>>(queries, keys);
    gemm_bf16<<<dim3(EMB_ / 64, MROWS / 32), 256>>>(blast, out);
}

// round 17
// speedup vs baseline: 1.0825x; 1.0825x over previous
#include <cuda_runtime.h>
#include <cuda_bf16.h>
#include <mma.h>
using namespace nvcuda;

#define B_    16
#define TQ_   128
#define TK_   128
#define EMB_  256
#define HID_  100
#define F2E_  512   // 2*EMB
#define MROWS (B_ * TK_)          // 2048
#define XROWS (2 * MROWS)         // 4096 fused (keys || queries)

// Scratch (allocation-free rule: __device__ globals)
__device__ float g_A[MROWS * HID_];            // A[b][i][h]
__device__ float g_Ct[B_ * HID_ * TQ_];        // C^T[b][h][j] (includes +b1)
__device__ __nv_bfloat16 g_Wlhi[EMB_ * F2E_];  // Wlast split (filled by pv)
__device__ __nv_bfloat16 g_Wllo[EMB_ * F2E_];
__device__ __nv_bfloat16 g_fhi[MROWS * F2E_];  // features split
__device__ __nv_bfloat16 g_flo[MROWS * F2E_];
__device__ __nv_bfloat16 g_Phi[MROWS * TQ_];   // softmax P split
__device__ __nv_bfloat16 g_Plo[MROWS * TQ_];

__device__ __forceinline__ float ftanh(float x) {
    float y;
    asm("tanh.approx.f32 %0, %1;" : "=f"(y) : "f"(x));
    return y;
}

__device__ __forceinline__ void bsplit(float v, __nv_bfloat16& hi,
                                       __nv_bfloat16& lo) {
    hi = __float2bfloat16(v);
    lo = __float2bfloat16(v - __bfloat162float(hi));
}

// split 4 floats -> 4 bf16 hi + 4 bf16 lo at the given addrs
__device__ __forceinline__ void split4_store(float4 v, __nv_bfloat16* hi,
                                             __nv_bfloat16* lo) {
    __nv_bfloat16 h0, h1, h2, h3, l0, l1, l2, l3;
    bsplit(v.x, h0, l0); bsplit(v.y, h1, l1);
    bsplit(v.z, h2, l2); bsplit(v.w, h3, l3);
    *(__nv_bfloat162*)(hi)     = __nv_bfloat162{h0, h1};
    *(__nv_bfloat162*)(hi + 2) = __nv_bfloat162{h2, h3};
    *(__nv_bfloat162*)(lo)     = __nv_bfloat162{l0, l1};
    *(__nv_bfloat162*)(lo + 2) = __nv_bfloat162{l2, l3};
}

#define ALD 48
#define BLD 48
#define CLD 68

typedef wmma::fragment<wmma::matrix_a, 16, 16, 16, __nv_bfloat16,
                       wmma::row_major> FragA;
typedef wmma::fragment<wmma::matrix_b, 16, 16, 16, __nv_bfloat16,
                       wmma::col_major> FragB;
typedef wmma::fragment<wmma::matrix_b, 16, 16, 16, __nv_bfloat16,
                       wmma::row_major> FragBr;
typedef wmma::fragment<wmma::accumulator, 16, 16, 16, float> FragC;

// ---------------------------------------------------------------------------
// K1: prep GEMM. A (keys/queries) and W1 split inline from fp32.
// Fused M=4096 rows (keys -> g_A; queries -> g_Ct + b1).
// grid (2 n-tiles, 128 m-tiles) = 256 blocks, 256 threads.
// ---------------------------------------------------------------------------
__global__ void __launch_bounds__(256) prep_bf16(
        const float* __restrict__ queries,
        const float* __restrict__ keys,
        const float* __restrict__ W1,
        const float* __restrict__ b1) {
    __shared__ __align__(16) __nv_bfloat16 Ah[2][32 * ALD], Al[2][32 * ALD];
    __shared__ __align__(16) __nv_bfloat16 Bh[2][64 * BLD], Bl[2][64 * BLD];
    __shared__ __align__(16) float cs[32 * CLD];

    int m0g = blockIdx.y * 32;
    int side = m0g >= MROWS;
    int m0 = m0g & (MROWS - 1);
    int n0 = blockIdx.x * 64;
    const float* Xp = side ? queries : keys;
    const float* Wp = W1 + side * EMB_;

    int tid = threadIdx.x;
    int ar = tid >> 3, ac = (tid & 7) * 4;   // A stage: 32 rows x 32 k
    int br = tid >> 2, bc = (tid & 3) * 8;   // B stage: 64 rows x 32 k
    int w = tid >> 5, wm = w & 1, wn = w >> 1;

    const float* A_src = Xp + (m0 + ar) * EMB_ + ac;
    int hB = n0 + br;
    bool bok = hB < HID_;
    const float* B_src = Wp + hB * F2E_ + bc;
    const float4 z4 = make_float4(0.f, 0.f, 0.f, 0.f);

    FragC c;
    wmma::fill_fragment(c, 0.f);
    FragA a_hi, a_lo;
    FragB b_hi, b_lo;

    float4 af  = *(const float4*)A_src;
    float4 bf0 = bok ? *(const float4*)B_src : z4;
    float4 bf1 = bok ? *(const float4*)(B_src + 4) : z4;
    split4_store(af, &Ah[0][ar * ALD + ac], &Al[0][ar * ALD + ac]);
    split4_store(bf0, &Bh[0][br * BLD + bc], &Bl[0][br * BLD + bc]);
    split4_store(bf1, &Bh[0][br * BLD + bc + 4], &Bl[0][br * BLD + bc + 4]);
    __syncthreads();

    const int NT = EMB_ / 32;  // 8
    #pragma unroll 1
    for (int t = 0; t < NT; ++t) {
        if (t + 1 < NT) {
            int k0 = (t + 1) * 32;
            af  = *(const float4*)(A_src + k0);
            bf0 = bok ? *(const float4*)(B_src + k0) : z4;
            bf1 = bok ? *(const float4*)(B_src + k0 + 4) : z4;
        }
        int bsel = t & 1;
        #pragma unroll
        for (int kk = 0; kk < 32; kk += 16) {
            wmma::load_matrix_sync(a_hi, &Ah[bsel][(wm * 16) * ALD + kk], ALD);
            wmma::load_matrix_sync(a_lo, &Al[bsel][(wm * 16) * ALD + kk], ALD);
            wmma::load_matrix_sync(b_hi, &Bh[bsel][(wn * 16) * BLD + kk], BLD);
            wmma::load_matrix_sync(b_lo, &Bl[bsel][(wn * 16) * BLD + kk], BLD);
            wmma::mma_sync(c, a_hi, b_hi, c);
            wmma::mma_sync(c, a_hi, b_lo, c);
            wmma::mma_sync(c, a_lo, b_hi, c);
        }
        if (t + 1 < NT) {
            int nb = (t + 1) & 1;
            split4_store(af, &Ah[nb][ar * ALD + ac], &Al[nb][ar * ALD + ac]);
            split4_store(bf0, &Bh[nb][br * BLD + bc], &Bl[nb][br * BLD + bc]);
            split4_store(bf1, &Bh[nb][br * BLD + bc + 4],
                         &Bl[nb][br * BLD + bc + 4]);
            __syncthreads();
        }
    }
    __syncthreads();
    wmma::store_matrix_sync(cs + (wm * 16) * CLD + wn * 16, c, CLD,
                            wmma::mem_row_major);
    __syncthreads();

    for (int e = tid; e < 32 * 64; e += 256) {
        int rw = e >> 6, col = e & 63;
        int h = n0 + col;
        if (h < HID_) {
            float v = cs[rw * CLD + col];
            int row = m0 + rw;
            if (!side) {
                g_A[row * HID_ + h] = v;
            } else {
                int b = row >> 7, j = row & 127;
                g_Ct[(b * HID_ + h) * TQ_ + j] = v + b1[h];
            }
        }
    }
}

// ---------------------------------------------------------------------------
// K2a: score MLP + softmax -> P (bf16 hi/lo), km folded in. PDL: syncs on
// prep before reading g_Ct/g_A; mask/W2 loads overlap prep's tail.
// One block per (b, 4-row i-tile): grid (32, 16) = 512 blocks, 256 threads.
// ---------------------------------------------------------------------------
#define ITILE 4
#define PST   5

__global__ void __launch_bounds__(256) sim_kernel(
        const float* __restrict__ qmask,
        const float* __restrict__ kmask,
        const float* __restrict__ W2) {
    extern __shared__ __align__(16) float sm[];
    float* c_s  = sm;                         // 12800
    float* a_s  = c_s + HID_ * TQ_;           // 400
    float* w2_s = a_s + ITILE * HID_;         // 104
    float* km_s = w2_s + 104;                 // 4
    float* p_s  = km_s + 4;                   // 128*5 = 640

    int b  = blockIdx.y;
    int i0 = blockIdx.x * ITILE;
    int tid = threadIdx.x;

    // --- prologue: independent input loads (overlap predecessor) ---
    if (tid < HID_)  w2_s[tid] = W2[tid];
    if (tid < ITILE) km_s[tid] = kmask[b * TK_ + i0 + tid];
    int j  = (tid & 63) * 2;   // query pair (j, j+1)
    int r  = tid >> 6;         // i-row (0..3)
    float2 qm2 = *(const float2*)(qmask + b * TQ_ + j);

    cudaGridDependencySynchronize();   // wait for prep's g_Ct/g_A

    {   // cooperative c-panel stage (float4, coalesced)
        const float4* src = (const float4*)(g_Ct + b * HID_ * TQ_);
        float4* dst = (float4*)c_s;
        #pragma unroll
        for (int s = 0; s < 13; ++s) {
            int idx = tid + 256 * s;
            if (idx < (HID_ * TQ_) / 4) dst[idx] = src[idx];
        }
    }
    for (int idx = tid; idx < ITILE * HID_; idx += 256)
        a_s[idx] = g_A[(b * TK_ + i0 + (idx / HID_)) * HID_ + (idx % HID_)];
    __syncthreads();

    // ---- phase 1: sim[r][j(+1)] = sum_h tanh(a[r,h] + c[h,j(+1)]) * w2[h]
    const float* ar_ = a_s + r * HID_;
    float acc0 = 0.f, acc1 = 0.f;
    #pragma unroll 4
    for (int h = 0; h < HID_; ++h) {
        float2 c2 = *(const float2*)&c_s[h * TQ_ + j];
        float av = ar_[h];
        float w  = w2_s[h];
        acc0 = fmaf(w, ftanh(av + c2.x), acc0);
        acc1 = fmaf(w, ftanh(av + c2.y), acc1);
    }
    const float NEGC = -4294967295.0f;  // -2^32 + 1
    p_s[j * PST + r]       = (qm2.x == 0.0f) ? NEGC : acc0;
    p_s[(j + 1) * PST + r] = (qm2.y == 0.0f) ? NEGC : acc1;
    __syncthreads();

    // ---- phase 2: softmax over j; warps 0..3 own rows 0..3, write P direct
    int warp = tid >> 5, lane = tid & 31;
    if (warp < ITILE) {
        int ii = warp;
        float v[4];
        float m = -3.4e38f;
        #pragma unroll
        for (int q = 0; q < 4; ++q) {
            v[q] = p_s[(lane + 32 * q) * PST + ii];
            m = fmaxf(m, v[q]);
        }
        #pragma unroll
        for (int off = 16; off; off >>= 1)
            m = fmaxf(m, __shfl_xor_sync(0xffffffffu, m, off));
        float ssum = 0.f;
        #pragma unroll
        for (int q = 0; q < 4; ++q) { v[q] = __expf(v[q] - m); ssum += v[q]; }
        #pragma unroll
        for (int off = 16; off; off >>= 1)
            ssum += __shfl_xor_sync(0xffffffffu, ssum, off);
        float scale = km_s[ii] / ssum;   // fold key_mask scalar into P
        int prow = (b * TK_ + i0 + ii) * TQ_;
        #pragma unroll
        for (int q = 0; q < 4; ++q) {
            __nv_bfloat16 hi, lo;
            bsplit(v[q] * scale, hi, lo);
            g_Phi[prow + lane + 32 * q] = hi;
            g_Plo[prow + lane + 32 * q] = lo;
        }
    }
}

// ---------------------------------------------------------------------------
// K2b: keys_attn = P @ queries (bf16 hi/lo tensor GEMM, K=128) + feature
// epilogue. Prologue (pre-sync): split Wlast into global (side job for gemm),
// split queries B-panel, prefetch keys. PDL sync before reading g_Phi/g_Plo.
// grid (4 n-tiles, 64 m-tiles) = 256 blocks.
// ---------------------------------------------------------------------------
#define PALD 136   // A smem ldm (bf16): 272B rows
#define PBLD 72    // B smem ldm (bf16): 144B rows

__global__ void __launch_bounds__(256) pv_kernel(
        const float* __restrict__ queries,
        const float* __restrict__ keys,
        const float* __restrict__ Wlast) {
    __shared__ __align__(16) __nv_bfloat16 Ah[32 * PALD], Al[32 * PALD];
    __shared__ __align__(16) __nv_bfloat16 Bh[TQ_ * PBLD], Bl[TQ_ * PBLD];
    __shared__ __align__(16) float cs[32 * CLD];

    int m0 = blockIdx.y * 32;          // global key row
    int n0 = blockIdx.x * 64;          // emb col
    int b  = m0 >> 7;
    int tid = threadIdx.x;
    int w = tid >> 5, wm = w & 1, wn = w >> 1;

    // --- prologue (independent of sim): Wlast split side-job for gemm ---
    {
        int gt = (blockIdx.y * gridDim.x + blockIdx.x) * 256 + tid;  // < 65536
        float2 wv = *(const float2*)(Wlast + gt * 2);
        __nv_bfloat16 h0, h1, l0, l1;
        bsplit(wv.x, h0, l0);
        bsplit(wv.y, h1, l1);
        *(__nv_bfloat162*)(g_Wlhi + gt * 2) = __nv_bfloat162{h0, h1};
        *(__nv_bfloat162*)(g_Wllo + gt * 2) = __nv_bfloat162{l0, l1};
    }
    // keys prefetch for epilogue
    int col0 = tid & 63, rw0 = tid >> 6;
    float kv[8];
    #pragma unroll
    for (int s = 0; s < 8; ++s)
        kv[s] = __ldg(keys + (m0 + rw0 + 4 * s) * EMB_ + n0 + col0);
    // stage B = queries_b[0..127][n0..n0+63], split inline from fp32
    #pragma unroll
    for (int s = 0; s < 4; ++s) {
        int cidx = tid + 256 * s;          // 1024 chunks of 8
        int r = cidx >> 3, c8 = (cidx & 7) * 8;
        const float* q = queries + (b * TQ_ + r) * EMB_ + n0 + c8;
        split4_store(*(const float4*)q,
                     &Bh[r * PBLD + c8], &Bl[r * PBLD + c8]);
        split4_store(*(const float4*)(q + 4),
                     &Bh[r * PBLD + c8 + 4], &Bl[r * PBLD + c8 + 4]);
    }

    cudaGridDependencySynchronize();   // wait for sim's g_Phi/g_Plo

    // stage A = P[m0..m0+31][0..127] (hi/lo, already bf16)
    #pragma unroll
    for (int s = 0; s < 2; ++s) {
        int cidx = tid + 256 * s;          // 512 chunks of 8
        int r = cidx >> 4, c8 = (cidx & 15) * 8;
        *(uint4*)&Ah[r * PALD + c8] = *(const uint4*)&g_Phi[(m0 + r) * TQ_ + c8];
        *(uint4*)&Al[r * PALD + c8] = *(const uint4*)&g_Plo[(m0 + r) * TQ_ + c8];
    }
    __syncthreads();

    FragC c;
    wmma::fill_fragment(c, 0.f);
    FragA a_hi, a_lo;
    FragBr b_hi, b_lo;
    #pragma unroll
    for (int kk = 0; kk < TQ_; kk += 16) {
        wmma::load_matrix_sync(a_hi, &Ah[(wm * 16) * PALD + kk], PALD);
        wmma::load_matrix_sync(a_lo, &Al[(wm * 16) * PALD + kk], PALD);
        wmma::load_matrix_sync(b_hi, &Bh[kk * PBLD + wn * 16], PBLD);
        wmma::load_matrix_sync(b_lo, &Bl[kk * PBLD + wn * 16], PBLD);
        wmma::mma_sync(c, a_hi, b_hi, c);
        wmma::mma_sync(c, a_hi, b_lo, c);
        wmma::mma_sync(c, a_lo, b_hi, c);
    }
    __syncthreads();
    wmma::store_matrix_sync(cs + (wm * 16) * CLD + wn * 16, c, CLD,
                            wmma::mem_row_major);
    __syncthreads();

    // feature epilogue: fm = ka*kv, fs = (ka-kv)^2, split to bf16
    #pragma unroll
    for (int s = 0; s < 8; ++s) {
        int rw = rw0 + 4 * s, col = col0;
        float ka = cs[rw * CLD + col];
        int row = m0 + rw;
        float fm = ka * kv[s];
        float d  = ka - kv[s];
        float fs = d * d;
        __nv_bfloat16 hi, lo;
        bsplit(fm, hi, lo);
        g_fhi[row * F2E_ + n0 + col] = hi;
        g_flo[row * F2E_ + n0 + col] = lo;
        bsplit(fs, hi, lo);
        g_fhi[row * F2E_ + EMB_ + n0 + col] = hi;
        g_flo[row * F2E_ + EMB_ + n0 + col] = lo;
    }
}

// ---------------------------------------------------------------------------
// K3: out = relu(feat[2048,512] @ Wlast[256,512]^T + blast).
// feat and Wlast pre-split bf16 (Wlast by pv's prologue). PDL sync first.
// grid (4, 64) = 256 blocks.
// ---------------------------------------------------------------------------
__global__ void __launch_bounds__(256) gemm_bf16(
        const float* __restrict__ blast,
        float* __restrict__ out) {
    __shared__ __align__(16) __nv_bfloat16 Ah[2][32 * ALD], Al[2][32 * ALD];
    __shared__ __align__(16) __nv_bfloat16 Bh[2][64 * BLD], Bl[2][64 * BLD];
    __shared__ __align__(16) float cs[32 * CLD];

    int m0 = blockIdx.y * 32;
    int n0 = blockIdx.x * 64;
    int tid = threadIdx.x;
    int ar = tid >> 3, ac = (tid & 7) * 4;
    int br = tid >> 2, bc = (tid & 3) * 8;
    int w = tid >> 5, wm = w & 1, wn = w >> 1;

    // prologue: independent load
    float bl = blast[n0 + (tid & 63)];

    cudaGridDependencySynchronize();   // wait for pv's g_f / g_Wl

    const __nv_bfloat16* Ah_src = g_fhi + (m0 + ar) * F2E_ + ac;
    const __nv_bfloat16* Al_src = g_flo + (m0 + ar) * F2E_ + ac;
    const __nv_bfloat16* Bh_src = g_Wlhi + (n0 + br) * F2E_ + bc;
    const __nv_bfloat16* Bl_src = g_Wllo + (n0 + br) * F2E_ + bc;

    FragC c;
    wmma::fill_fragment(c, 0.f);
    FragA a_hi, a_lo;
    FragB b_hi, b_lo;

    uint2 avh = *(const uint2*)Ah_src;
    uint2 avl = *(const uint2*)Al_src;
    uint4 bvh = *(const uint4*)Bh_src;
    uint4 bvl = *(const uint4*)Bl_src;
    *(uint2*)&Ah[0][ar * ALD + ac] = avh;
    *(uint2*)&Al[0][ar * ALD + ac] = avl;
    *(uint4*)&Bh[0][br * BLD + bc] = bvh;
    *(uint4*)&Bl[0][br * BLD + bc] = bvl;
    __syncthreads();

    const int NT = F2E_ / 32;  // 16
    #pragma unroll 1
    for (int t = 0; t < NT; ++t) {
        if (t + 1 < NT) {
            int k0 = (t + 1) * 32;
            avh = *(const uint2*)(Ah_src + k0);
            avl = *(const uint2*)(Al_src + k0);
            bvh = *(const uint4*)(Bh_src + k0);
            bvl = *(const uint4*)(Bl_src + k0);
        }
        int bsel = t & 1;
        #pragma unroll
        for (int kk = 0; kk < 32; kk += 16) {
            wmma::load_matrix_sync(a_hi, &Ah[bsel][(wm * 16) * ALD + kk], ALD);
            wmma::load_matrix_sync(a_lo, &Al[bsel][(wm * 16) * ALD + kk], ALD);
            wmma::load_matrix_sync(b_hi, &Bh[bsel][(wn * 16) * BLD + kk], BLD);
            wmma::load_matrix_sync(b_lo, &Bl[bsel][(wn * 16) * BLD + kk], BLD);
            wmma::mma_sync(c, a_hi, b_hi, c);
            wmma::mma_sync(c, a_hi, b_lo, c);
            wmma::mma_sync(c, a_lo, b_hi, c);
        }
        if (t + 1 < NT) {
            int nb = (t + 1) & 1;
            *(uint2*)&Ah[nb][ar * ALD + ac] = avh;
            *(uint2*)&Al[nb][ar * ALD + ac] = avl;
            *(uint4*)&Bh[nb][br * BLD + bc] = bvh;
            *(uint4*)&Bl[nb][br * BLD + bc] = bvl;
            __syncthreads();
        }
    }
    __syncthreads();
    wmma::store_matrix_sync(cs + (wm * 16) * CLD + wn * 16, c, CLD,
                            wmma::mem_row_major);
    __syncthreads();

    for (int e = tid; e < 32 * 64; e += 256) {
        int rw = e >> 6, col = e & 63;
        float bcol = __shfl_sync(0xffffffffu, bl, 0, 32);  // unused lane trick
        (void)bcol;
        float v = cs[rw * CLD + col] + blast[n0 + col];
        out[(m0 + rw) * EMB_ + n0 + col] = fmaxf(v, 0.f);
    }
}

// ---------------------------------------------------------------------------
extern "C" void kernel_launch(void* const* d_in, const int* in_sizes, int n_in,
                              void* d_out, int out_size) {
    const float* queries = (const float*)d_in[0];
    const float* keys    = (const float*)d_in[1];
    const float* qmask   = (const float*)d_in[2];
    const float* kmask   = (const float*)d_in[3];
    const float* W1      = (const float*)d_in[4];
    const float* b1      = (const float*)d_in[5];
    const float* W2      = (const float*)d_in[6];
    const float* Wlast   = (const float*)d_in[7];
    const float* blast   = (const float*)d_in[8];
    float* out = (float*)d_out;

    const int smem_sim = (HID_ * TQ_ + ITILE * HID_ + 104 + ITILE + TQ_ * PST) * 4;
    cudaFuncSetAttribute(sim_kernel, cudaFuncAttributeMaxDynamicSharedMemorySize,
                         smem_sim);

    // K1: plain launch (no predecessor)
    prep_bf16<<<dim3(2, XROWS / 32), 256>>>(queries, keys, W1, b1);

    // PDL attribute for dependent launches
    cudaLaunchAttribute attrs[1];
    attrs[0].id = cudaLaunchAttributeProgrammaticStreamSerialization;
    attrs[0].val.programmaticStreamSerializationAllowed = 1;

    {   // sim
        cudaLaunchConfig_t cfg = {};
        cfg.gridDim = dim3(TK_ / ITILE, B_);
        cfg.blockDim = dim3(256);
        cfg.dynamicSmemBytes = smem_sim;
        cfg.attrs = attrs;
        cfg.numAttrs = 1;
        cudaLaunchKernelEx(&cfg, sim_kernel, qmask, kmask, W2);
    }
    {   // pv
        cudaLaunchConfig_t cfg = {};
        cfg.gridDim = dim3(EMB_ / 64, MROWS / 32);
        cfg.blockDim = dim3(256);
        cfg.attrs = attrs;
        cfg.numAttrs = 1;
        cudaLaunchKernelEx(&cfg, pv_kernel, queries, keys, Wlast);
    }
    {   // gemm
        cudaLaunchConfig_t cfg = {};
        cfg.gridDim = dim3(EMB_ / 64, MROWS / 32);
        cfg.blockDim = dim3(256);
        cfg.attrs = attrs;
        cfg.numAttrs = 1;
        cudaLaunchKernelEx(&cfg, gemm_bf16, blast, out);
    }
}